// round 13
// baseline (speedup 1.0000x reference)
#include <cuda_runtime.h>
#include <cuda_bf16.h>
#include <cstdint>

#define NNODES 65536
#define NEDGES 262144

// ============================ device scratch ============================
__device__ __align__(256) __nv_bfloat16 g_xb   [NNODES * 256];
__device__ __align__(256) __nv_bfloat16 g_hnode[NNODES * 128];
__device__ __align__(256) __nv_bfloat16 g_grow [NNODES * 256];
__device__ __align__(256) __nv_bfloat16 g_gcol [NNODES * 256];
__device__ __align__(256) __nv_bfloat16 g_h0   [(size_t)NEDGES * 256];
__device__ __align__(256) __nv_bfloat16 g_Bx [128 * 256];
__device__ __align__(256) __nv_bfloat16 g_B0a[256 * 128];
__device__ __align__(256) __nv_bfloat16 g_B0b[256 * 128];
__device__ __align__(256) __nv_bfloat16 g_Bm [8][256 * 256];
__device__ int g_idx64;

// ============================ PTX helpers (base PTX only) ============================
__device__ __forceinline__ uint32_t smem_u32(const void* p) {
    uint32_t a;
    asm("{ .reg .u64 t; cvta.to.shared.u64 t, %1; cvt.u32.u64 %0, t; }" : "=r"(a) : "l"(p));
    return a;
}
__device__ __forceinline__ void cp16(uint32_t dst, const void* src) {
    asm volatile("cp.async.cg.shared.global [%0], [%1], 16;" :: "r"(dst), "l"(src));
}
__device__ __forceinline__ void cp_commit() {
    asm volatile("cp.async.commit_group;" ::: "memory");
}
template <int N>
__device__ __forceinline__ void cp_wait() {
    asm volatile("cp.async.wait_group %0;" :: "n"(N) : "memory");
}
__device__ __forceinline__ void ldm_x4(uint32_t* r, uint32_t addr) {
    asm volatile("ldmatrix.sync.aligned.m8n8.x4.shared.b16 {%0,%1,%2,%3}, [%4];"
                 : "=r"(r[0]), "=r"(r[1]), "=r"(r[2]), "=r"(r[3]) : "r"(addr));
}
__device__ __forceinline__ void ldm_x2(uint32_t* r, uint32_t addr) {
    asm volatile("ldmatrix.sync.aligned.m8n8.x2.shared.b16 {%0,%1}, [%2];"
                 : "=r"(r[0]), "=r"(r[1]) : "r"(addr));
}
__device__ __forceinline__ void mma_bf16(float* c, const uint32_t* a, const uint32_t* b) {
    asm volatile(
        "mma.sync.aligned.m16n8k16.row.col.f32.bf16.bf16.f32 "
        "{%0,%1,%2,%3}, {%4,%5,%6,%7}, {%8,%9}, {%0,%1,%2,%3};"
        : "+f"(c[0]), "+f"(c[1]), "+f"(c[2]), "+f"(c[3])
        : "r"(a[0]), "r"(a[1]), "r"(a[2]), "r"(a[3]), "r"(b[0]), "r"(b[1]));
}

// ============================ prep: weights + x conversion + idx detect (one launch) ============================
// blocks [0,608): 32x32 weight transpose tiles; ALL 4096 blocks: grid-stride x -> bf16.
__global__ void prep_all(const float* __restrict__ x, const float* __restrict__ Wx,
                         const float* __restrict__ W0, const float* __restrict__ Wm,
                         const unsigned* __restrict__ ei) {
    __shared__ float tile[32][33];
    const int tid = threadIdx.x;
    if (blockIdx.x == 0 && tid == 0) {
        int is64 = 1;
        for (int i = 0; i < 512; i++)
            if (ei[2 * i + 1] != 0u) { is64 = 0; break; }
        g_idx64 = is64;
    }
    const int bid = blockIdx.x;
    if (bid < 608) {
        const float* W; __nv_bfloat16* B;
        int row0, ldW, Ksrc, Kpad, tn, tk;
        if (bid < 32)       { W = Wx; B = g_Bx;  row0 = 0;   ldW = 128; Ksrc = 256; Kpad = 256; tn = bid >> 3;         tk = bid & 7; }
        else if (bid < 64)  { W = W0; B = g_B0a; row0 = 0;   ldW = 256; Ksrc = 128; Kpad = 128; tn = (bid - 32) >> 2;  tk = (bid - 32) & 3; }
        else if (bid < 96)  { W = W0; B = g_B0b; row0 = 128; ldW = 256; Ksrc = 128; Kpad = 128; tn = (bid - 64) >> 2;  tk = (bid - 64) & 3; }
        else {
            int b = bid - 96, L = b >> 6, t = b & 63;
            W = Wm + (size_t)L * 65536; B = &g_Bm[L][0];
            row0 = 0; ldW = 256; Ksrc = 256; Kpad = 256; tn = t >> 3; tk = t & 7;
        }
        const int n0 = tn * 32, k0 = tk * 32;
        const int tx = tid & 31, ty = tid >> 5;     // 32 x 8
        #pragma unroll
        for (int r = 0; r < 32; r += 8) {
            int k = k0 + ty + r;
            tile[ty + r][tx] = (k < Ksrc) ? W[(size_t)(row0 + k) * ldW + n0 + tx] : 0.f;
        }
        __syncthreads();
        #pragma unroll
        for (int r = 0; r < 32; r += 8) {
            int n = n0 + ty + r;
            B[(size_t)n * Kpad + k0 + tx] = __float2bfloat16(tile[tx][ty + r]);
        }
    }
    for (int i = blockIdx.x * blockDim.x + tid; i < NNODES * 256; i += gridDim.x * blockDim.x)
        g_xb[i] = __float2bfloat16(x[i]);
}

// ============================ generic bf16 HMMA GEMM (prep stages) ============================
template <int K, int NOUT, bool LEAKY, bool HASBIAS, bool DUAL>
__global__ void __launch_bounds__(256)
gemm_mma(const __nv_bfloat16* __restrict__ A, const __nv_bfloat16* __restrict__ Bin,
         const __nv_bfloat16* __restrict__ B2, const float* __restrict__ bias,
         __nv_bfloat16* __restrict__ Out1, __nv_bfloat16* __restrict__ Out2) {
    static_assert(K % 64 == 0, "");
    constexpr int KT = K / 64;
    extern __shared__ char smem[];
    const uint32_t sb = smem_u32(smem);
    constexpr uint32_t STAGE = 32768, BOFF = 16384;

    const __nv_bfloat16* B = (DUAL && blockIdx.z) ? B2 : Bin;
    __nv_bfloat16* Out = (DUAL && blockIdx.z) ? Out2 : Out1;

    const int tid = threadIdx.x;
    const int lane = tid & 31, warp = tid >> 5;
    const int warp_m = warp & 1;
    const int warp_n = warp >> 1;
    const size_t m0 = (size_t)blockIdx.x * 128;
    const int n0 = blockIdx.y * 128;

    float acc[4][4][4];
    #pragma unroll
    for (int i = 0; i < 4; i++)
        #pragma unroll
        for (int j = 0; j < 4; j++)
            #pragma unroll
            for (int q = 0; q < 4; q++) acc[i][j][q] = 0.f;

    auto load_stage = [&](int stage, int kt) {
        const uint32_t base = sb + stage * STAGE;
        #pragma unroll
        for (int i = 0; i < 4; i++) {
            int idx = tid + i * 256;
            int r = idx >> 3, c8 = idx & 7;
            uint32_t dst = base + r * 128 + (((c8 ^ (r & 7))) << 4);
            cp16(dst, A + (m0 + r) * K + kt * 64 + c8 * 8);
        }
        #pragma unroll
        for (int i = 0; i < 4; i++) {
            int idx = tid + i * 256;
            int r = idx >> 3, c8 = idx & 7;
            uint32_t dst = base + BOFF + r * 128 + (((c8 ^ (r & 7))) << 4);
            cp16(dst, B + (size_t)(n0 + r) * K + kt * 64 + c8 * 8);
        }
    };

    load_stage(0, 0);
    cp_commit();

    for (int kt = 0; kt < KT; kt++) {
        if (kt + 1 < KT) { load_stage((kt + 1) & 1, kt + 1); cp_commit(); cp_wait<1>(); }
        else             { cp_wait<0>(); }
        __syncthreads();

        const uint32_t abase = sb + (kt & 1) * STAGE;
        const uint32_t bbase = abase + BOFF;
        #pragma unroll
        for (int ks = 0; ks < 4; ks++) {
            uint32_t af[4][4];
            #pragma unroll
            for (int mi = 0; mi < 4; mi++) {
                int r = warp_m * 64 + mi * 16 + (lane & 15);
                int c8 = ks * 2 + (lane >> 4);
                ldm_x4(af[mi], abase + r * 128 + ((c8 ^ (r & 7)) << 4));
            }
            uint32_t bf2[4][2];
            #pragma unroll
            for (int ni = 0; ni < 4; ni++) {
                int r = warp_n * 32 + ni * 8 + (lane & 7);
                int c8 = ks * 2 + ((lane >> 3) & 1);
                ldm_x2(bf2[ni], bbase + r * 128 + ((c8 ^ (r & 7)) << 4));
            }
            #pragma unroll
            for (int mi = 0; mi < 4; mi++)
                #pragma unroll
                for (int ni = 0; ni < 4; ni++)
                    mma_bf16(acc[mi][ni], af[mi], bf2[ni]);
        }
        __syncthreads();
    }

    const int g = lane >> 2;
    #pragma unroll
    for (int ni = 0; ni < 4; ni++) {
        const int col = n0 + warp_n * 32 + ni * 8 + ((lane & 3) << 1);
        float bb0 = 0.f, bb1 = 0.f;
        if (HASBIAS) { bb0 = __ldg(bias + col); bb1 = __ldg(bias + col + 1); }
        #pragma unroll
        for (int mi = 0; mi < 4; mi++) {
            const size_t r0 = m0 + warp_m * 64 + mi * 16 + g;
            float v0 = acc[mi][ni][0] + bb0, v1 = acc[mi][ni][1] + bb1;
            float v2 = acc[mi][ni][2] + bb0, v3 = acc[mi][ni][3] + bb1;
            if (LEAKY) {
                v0 = v0 >= 0.f ? v0 : 0.01f * v0;  v1 = v1 >= 0.f ? v1 : 0.01f * v1;
                v2 = v2 >= 0.f ? v2 : 0.01f * v2;  v3 = v3 >= 0.f ? v3 : 0.01f * v3;
            }
            __nv_bfloat162 p0 = __floats2bfloat162_rn(v0, v1);
            __nv_bfloat162 p1 = __floats2bfloat162_rn(v2, v3);
            *(uint32_t*)(Out + r0 * NOUT + col)       = *(uint32_t*)&p0;
            *(uint32_t*)(Out + (r0 + 8) * NOUT + col) = *(uint32_t*)&p1;
        }
    }
}

// ============================ gather + ea-matvec + combine (256 edges/block) ============================
__global__ void __launch_bounds__(256)
gather_combine_ea(const int* __restrict__ ei, const float* __restrict__ ea,
                  const float* __restrict__ W0, const float* __restrict__ b0,
                  const __nv_bfloat16* __restrict__ gr, const __nv_bfloat16* __restrict__ gc,
                  __nv_bfloat16* __restrict__ h0) {
    __shared__ float sea[256][16];
    __shared__ int srow[256], scol[256];
    const int t = threadIdx.x;
    const long e0 = (long)blockIdx.x * 256;
    const int is64 = g_idx64;
    {
        long e = e0 + t;
        if (is64) { srow[t] = ei[2 * e]; scol[t] = ei[2 * (NEDGES + e)]; }
        else      { srow[t] = ei[e];     scol[t] = ei[NEDGES + e]; }
    }
    #pragma unroll
    for (int q = 0; q < 4; q++) {       // 1024 float4 loads, coalesced
        int f = t + q * 256;
        int e = f >> 2, k4 = f & 3;
        *(float4*)&sea[e][k4 * 4] = *(const float4*)(ea + (e0 + e) * 16 + k4 * 4);
    }
    const int cp = t & 127;             // column pair this thread owns
    float2 w[16];                       // W0c[:, 2cp..2cp+1] (rows 256..271 of W0)
    #pragma unroll
    for (int k = 0; k < 16; k++)
        w[k] = *(const float2*)(W0 + (size_t)(256 + k) * 256 + 2 * cp);
    const float2 bb = *(const float2*)(b0 + 2 * cp);
    __syncthreads();

    const int eo = t >> 7;
    #pragma unroll 4
    for (int i = eo; i < 256; i += 2) {
        float v0 = bb.x, v1 = bb.y;
        #pragma unroll
        for (int k = 0; k < 16; k++) {
            float s = sea[i][k];
            v0 += s * w[k].x;
            v1 += s * w[k].y;
        }
        const __nv_bfloat162 gv = ((const __nv_bfloat162*)(gr + (size_t)srow[i] * 256))[cp];
        const __nv_bfloat162 cv = ((const __nv_bfloat162*)(gc + (size_t)scol[i] * 256))[cp];
        float2 gb = __bfloat1622float2(gv);
        float2 cb = __bfloat1622float2(cv);
        v0 += gb.x + cb.x;
        v1 += gb.y + cb.y;
        v0 = v0 >= 0.f ? v0 : 0.01f * v0;
        v1 = v1 >= 0.f ? v1 : 0.01f * v1;
        ((__nv_bfloat162*)(h0 + (size_t)(e0 + i) * 256))[cp] = __floats2bfloat162_rn(v0, v1);
    }
}

// ============================ fused 8 mid layers + head (paired groups, named barriers) ============================
// Frozen at the R11 winner: 512 threads, warp grid 4(M)x4(N), SMEM activations,
// 4x32KB ring with 64KB paired groups, 2 full + 1 named barrier per layer.
__global__ void __launch_bounds__(512, 1)
fused_mid(const __nv_bfloat16* __restrict__ h0, const __nv_bfloat16* __restrict__ Bm,
          const float* __restrict__ bm, const float* __restrict__ Wl,
          const float* __restrict__ bl, float* __restrict__ out) {
    extern __shared__ char smem[];
    const uint32_t sb = smem_u32(smem);
    constexpr uint32_t RINGOFF = 65536;               // ring: 4 x 32KB at [64K, 192K)
    constexpr uint32_t PARAM = 65536 + 131072;
    float* sbias = (float*)(smem + PARAM);            // 8 x 256 fp32
    float* sWl   = (float*)(smem + PARAM + 8192);     // 256 x 3 fp32
    float* sbl   = (float*)(smem + PARAM + 8192 + 3072);

    const int tid = threadIdx.x, lane = tid & 31, warp = tid >> 5;
    const int warp_m = warp >> 2;                     // 0..3 -> M offset *32
    const int warp_n = warp & 3;                      // 0..3 -> N offset *64
    const size_t m0 = (size_t)blockIdx.x * 128;

    for (int i = tid; i < 2048; i += 512) sbias[i] = bm[i];
    for (int i = tid; i < 768; i += 512) sWl[i] = Wl[i];
    if (tid < 3) sbl[tid] = bl[tid];

    auto loadB = [&](int s) {
        const uint32_t base = sb + RINGOFF + (uint32_t)(s & 3) * 32768u;
        const __nv_bfloat16* src = Bm + (size_t)(s >> 2) * 65536 + (s & 3) * 64;
        #pragma unroll
        for (int i = 0; i < 4; i++) {
            int idx = tid + i * 512;
            int r = idx >> 3, c8 = idx & 7;
            cp16(base + r * 128 + ((c8 ^ (r & 7)) << 4), src + (size_t)r * 256 + c8 * 8);
        }
    };

    // A tile (h0, 128x256) -> A region as 4 chunks of [128][64], XOR swizzle
    #pragma unroll
    for (int kc = 0; kc < 4; kc++)
        #pragma unroll
        for (int i = 0; i < 2; i++) {
            int idx = tid + i * 512;
            int r = idx >> 3, c8 = idx & 7;
            cp16(sb + kc * 16384 + r * 128 + ((c8 ^ (r & 7)) << 4),
                 h0 + (m0 + r) * 256 + kc * 64 + c8 * 8);
        }
    loadB(0); loadB(1);
    cp_commit();                 // C1 = A + group0

    const int g = lane >> 2, j = lane & 3;
    const int rr_lo = ((lane >> 4) << 3) + (lane & 7);
    const int ar_lo = warp_m * 32 + (lane & 15);

    for (int l = 0; l < 8; ++l) {
        float acc[2][8][4];
        #pragma unroll
        for (int nt = 0; nt < 8; nt++) {
            float2 bb = *(const float2*)(sbias + (l << 8) + warp_n * 64 + 8 * nt + 2 * j);
            #pragma unroll
            for (int mi = 0; mi < 2; mi++) {
                acc[mi][nt][0] = bb.x; acc[mi][nt][1] = bb.y;
                acc[mi][nt][2] = bb.x; acc[mi][nt][3] = bb.y;
            }
        }
        #pragma unroll
        for (int gg = 0; gg < 2; gg++) {
            const int grp = 2 * l + gg;
            cp_wait<0>();
            __syncthreads();
            if (grp + 1 < 16) { loadB(2 * (grp + 1)); loadB(2 * (grp + 1) + 1); }
            cp_commit();
            #pragma unroll
            for (int khh = 0; khh < 2; khh++) {
                const int kh = gg * 2 + khh;
                const int s = l * 4 + kh;
                const uint32_t bbase = sb + RINGOFF + (uint32_t)(s & 3) * 32768u;
                const uint32_t achk = sb + kh * 16384;
                #pragma unroll
                for (int ksl = 0; ksl < 4; ksl++) {
                    const int cca = ksl * 2 + (lane >> 4);
                    uint32_t a0[4], a1[4];
                    int r0 = ar_lo;
                    ldm_x4(a0, achk + r0 * 128 + ((cca ^ (r0 & 7)) << 4));
                    int r1 = ar_lo + 16;
                    ldm_x4(a1, achk + r1 * 128 + ((cca ^ (r1 & 7)) << 4));
                    const int ccb = ksl * 2 + ((lane >> 3) & 1);
                    #pragma unroll
                    for (int bt = 0; bt < 4; bt++) {
                        int rr = warp_n * 64 + bt * 16 + rr_lo;
                        uint32_t bf[4];
                        ldm_x4(bf, bbase + rr * 128 + ((ccb ^ (rr & 7)) << 4));
                        mma_bf16(acc[0][2 * bt],     a0, bf);
                        mma_bf16(acc[0][2 * bt + 1], a0, bf + 2);
                        mma_bf16(acc[1][2 * bt],     a1, bf);
                        mma_bf16(acc[1][2 * bt + 1], a1, bf + 2);
                    }
                }
            }
        }
        asm volatile("bar.sync %0, %1;" :: "r"(1 + warp_m), "r"(128) : "memory");
        #pragma unroll
        for (int mi = 0; mi < 2; mi++) {
            const int r  = warp_m * 32 + mi * 16 + g;
            const int r2 = r + 8;
            #pragma unroll
            for (int nt = 0; nt < 8; nt++) {
                float v0 = acc[mi][nt][0], v1 = acc[mi][nt][1];
                float v2 = acc[mi][nt][2], v3 = acc[mi][nt][3];
                v0 = v0 >= 0.f ? v0 : 0.01f * v0;  v1 = v1 >= 0.f ? v1 : 0.01f * v1;
                v2 = v2 >= 0.f ? v2 : 0.01f * v2;  v3 = v3 >= 0.f ? v3 : 0.01f * v3;
                __nv_bfloat162 p0 = __floats2bfloat162_rn(v0, v1);
                __nv_bfloat162 p1 = __floats2bfloat162_rn(v2, v3);
                const int c = warp_n * 64 + nt * 8;
                const int kc = c >> 6, c8s = (c >> 3) & 7;
                *(uint32_t*)(smem + kc * 16384 + r * 128 + ((c8s ^ (r & 7)) << 4) + 4 * j) =
                    *(uint32_t*)&p0;
                *(uint32_t*)(smem + kc * 16384 + r2 * 128 + ((c8s ^ (r2 & 7)) << 4) + 4 * j) =
                    *(uint32_t*)&p1;
            }
        }
    }
    __syncthreads();

    // ---- fused head (warps 0-7): logits + log_softmax ----
    if (warp < 8) {
        uint32_t pa[32][2];
        #pragma unroll
        for (int s = 0; s < 16; s++) {
            int rr = warp * 16 + (lane & 15);
            int cc = (s & 3) * 2 + (lane >> 4);
            uint32_t f[4];
            ldm_x4(f, sb + (s >> 2) * 16384 + rr * 128 + ((cc ^ (rr & 7)) << 4));
            pa[2 * s][0] = f[0]; pa[2 * s][1] = f[1];
            pa[2 * s + 1][0] = f[2]; pa[2 * s + 1][1] = f[3];
        }
        float a3[2][3] = {{0.f, 0.f, 0.f}, {0.f, 0.f, 0.f}};
        #pragma unroll
        for (int t = 0; t < 32; t++) {
            float2 x = __bfloat1622float2(*(__nv_bfloat162*)&pa[t][0]);
            float2 y = __bfloat1622float2(*(__nv_bfloat162*)&pa[t][1]);
            const int c0 = 8 * t + 2 * j;
            float w00 = sWl[c0 * 3 + 0], w01 = sWl[c0 * 3 + 1], w02 = sWl[c0 * 3 + 2];
            float w10 = sWl[c0 * 3 + 3], w11 = sWl[c0 * 3 + 4], w12 = sWl[c0 * 3 + 5];
            a3[0][0] += x.x * w00 + x.y * w10;
            a3[0][1] += x.x * w01 + x.y * w11;
            a3[0][2] += x.x * w02 + x.y * w12;
            a3[1][0] += y.x * w00 + y.y * w10;
            a3[1][1] += y.x * w01 + y.y * w11;
            a3[1][2] += y.x * w02 + y.y * w12;
        }
        #pragma unroll
        for (int off = 1; off <= 2; off <<= 1) {
            #pragma unroll
            for (int r = 0; r < 2; r++)
                #pragma unroll
                for (int c = 0; c < 3; c++)
                    a3[r][c] += __shfl_xor_sync(0xffffffffu, a3[r][c], off);
        }
        if (j == 0) {
            const float bb0 = sbl[0], bb1 = sbl[1], bb2 = sbl[2];
            #pragma unroll
            for (int r = 0; r < 2; r++) {
                size_t e = m0 + warp * 16 + g + 8 * r;
                float l0 = a3[r][0] + bb0, l1 = a3[r][1] + bb1, l2 = a3[r][2] + bb2;
                float m = fmaxf(l0, fmaxf(l1, l2));
                float ls = m + logf(expf(l0 - m) + expf(l1 - m) + expf(l2 - m));
                out[e * 3 + 0] = l0 - ls;
                out[e * 3 + 1] = l1 - ls;
                out[e * 3 + 2] = l2 - ls;
            }
        }
    }
}

// ============================ host ============================
extern "C" void kernel_launch(void* const* d_in, const int* in_sizes, int n_in,
                              void* d_out, int out_size) {
    const float* x  = (const float*)d_in[0];
    const int*   ei = (const int*)d_in[1];
    const float* ea = (const float*)d_in[2];
    const float* Wx = (const float*)d_in[3];
    const float* bx = (const float*)d_in[4];
    const float* W0 = (const float*)d_in[5];
    const float* b0 = (const float*)d_in[6];
    const float* Wm = (const float*)d_in[7];
    const float* bm = (const float*)d_in[8];
    const float* Wl = (const float*)d_in[9];
    const float* bl = (const float*)d_in[10];
    float* out = (float*)d_out;

    void* p;
    cudaGetSymbolAddress(&p, g_xb);    __nv_bfloat16* xb    = (__nv_bfloat16*)p;
    cudaGetSymbolAddress(&p, g_hnode); __nv_bfloat16* hnode = (__nv_bfloat16*)p;
    cudaGetSymbolAddress(&p, g_grow);  __nv_bfloat16* grow  = (__nv_bfloat16*)p;
    cudaGetSymbolAddress(&p, g_gcol);  __nv_bfloat16* gcol  = (__nv_bfloat16*)p;
    cudaGetSymbolAddress(&p, g_h0);    __nv_bfloat16* h0p   = (__nv_bfloat16*)p;
    cudaGetSymbolAddress(&p, g_Bx);    __nv_bfloat16* Bx    = (__nv_bfloat16*)p;
    cudaGetSymbolAddress(&p, g_B0a);   __nv_bfloat16* B0a   = (__nv_bfloat16*)p;
    cudaGetSymbolAddress(&p, g_B0b);   __nv_bfloat16* B0b   = (__nv_bfloat16*)p;
    cudaGetSymbolAddress(&p, g_Bm);    __nv_bfloat16* Bm    = (__nv_bfloat16*)p;

    constexpr int SMEM = 65536;
    constexpr int FSMEM = 65536 + 131072 + 8192 + 3072 + 16;   // 207,904
    cudaFuncSetAttribute(gemm_mma<256, 128, true,  true,  false>, cudaFuncAttributeMaxDynamicSharedMemorySize, SMEM);
    cudaFuncSetAttribute(gemm_mma<128, 256, false, false, true >, cudaFuncAttributeMaxDynamicSharedMemorySize, SMEM);
    cudaFuncSetAttribute(fused_mid, cudaFuncAttributeMaxDynamicSharedMemorySize, FSMEM);

    // 1: all prep (weight transposes + x -> bf16 + idx detect)
    prep_all<<<4096, 256>>>(x, Wx, W0, Wm, (const unsigned*)ei);
    // 2: node MLP: h_node = leaky(x @ Wx + bx)
    gemm_mma<256, 128, true, true, false><<<dim3(NNODES / 128, 1, 1), 256, SMEM>>>(
        xb, Bx, nullptr, bx, hnode, nullptr);
    // 3: node-level edge-GEMM precompute: grow/gcol in one dual launch
    gemm_mma<128, 256, false, false, true><<<dim3(NNODES / 128, 2, 2), 256, SMEM>>>(
        hnode, B0a, B0b, nullptr, grow, gcol);
    // 4: gather + ea matvec + combine + leaky -> h0 (256 edges/block)
    gather_combine_ea<<<NEDGES / 256, 256>>>(ei, ea, W0, b0, grow, gcol, h0p);
    // 5: fused: 8 hidden layers + head + log_softmax
    fused_mid<<<NEDGES / 128, 512, FSMEM>>>(h0p, Bm, bm, Wl, bl, out);
}

// round 14
// speedup vs baseline: 1.0188x; 1.0188x over previous
#include <cuda_runtime.h>
#include <cuda_bf16.h>
#include <cstdint>

#define NNODES 65536
#define NEDGES 262144

// ============================ device scratch ============================
__device__ __align__(256) __nv_bfloat16 g_xb   [NNODES * 256];
__device__ __align__(256) __nv_bfloat16 g_hnode[NNODES * 128];
__device__ __align__(256) __nv_bfloat16 g_grow [NNODES * 256];
__device__ __align__(256) __nv_bfloat16 g_gcol [NNODES * 256];
__device__ __align__(256) __nv_bfloat16 g_h0   [(size_t)NEDGES * 256];
__device__ __align__(256) __nv_bfloat16 g_Bx [128 * 256];
__device__ __align__(256) __nv_bfloat16 g_B0a[256 * 128];
__device__ __align__(256) __nv_bfloat16 g_B0b[256 * 128];
__device__ __align__(256) __nv_bfloat16 g_B0c[256 * 16];   // W0c^T: [n][k], k contiguous
__device__ __align__(256) __nv_bfloat16 g_Bm [8][256 * 256];
__device__ int g_idx64;

// ============================ PTX helpers (base PTX only) ============================
__device__ __forceinline__ uint32_t smem_u32(const void* p) {
    uint32_t a;
    asm("{ .reg .u64 t; cvta.to.shared.u64 t, %1; cvt.u32.u64 %0, t; }" : "=r"(a) : "l"(p));
    return a;
}
__device__ __forceinline__ void cp16(uint32_t dst, const void* src) {
    asm volatile("cp.async.cg.shared.global [%0], [%1], 16;" :: "r"(dst), "l"(src));
}
__device__ __forceinline__ void cp_commit() {
    asm volatile("cp.async.commit_group;" ::: "memory");
}
template <int N>
__device__ __forceinline__ void cp_wait() {
    asm volatile("cp.async.wait_group %0;" :: "n"(N) : "memory");
}
__device__ __forceinline__ void ldm_x4(uint32_t* r, uint32_t addr) {
    asm volatile("ldmatrix.sync.aligned.m8n8.x4.shared.b16 {%0,%1,%2,%3}, [%4];"
                 : "=r"(r[0]), "=r"(r[1]), "=r"(r[2]), "=r"(r[3]) : "r"(addr));
}
__device__ __forceinline__ void ldm_x2(uint32_t* r, uint32_t addr) {
    asm volatile("ldmatrix.sync.aligned.m8n8.x2.shared.b16 {%0,%1}, [%2];"
                 : "=r"(r[0]), "=r"(r[1]) : "r"(addr));
}
__device__ __forceinline__ void mma_bf16(float* c, const uint32_t* a, const uint32_t* b) {
    asm volatile(
        "mma.sync.aligned.m16n8k16.row.col.f32.bf16.bf16.f32 "
        "{%0,%1,%2,%3}, {%4,%5,%6,%7}, {%8,%9}, {%0,%1,%2,%3};"
        : "+f"(c[0]), "+f"(c[1]), "+f"(c[2]), "+f"(c[3])
        : "r"(a[0]), "r"(a[1]), "r"(a[2]), "r"(a[3]), "r"(b[0]), "r"(b[1]));
}

// ============================ prep: weights + x conversion + idx detect (one launch) ============================
__global__ void prep_all(const float* __restrict__ x, const float* __restrict__ Wx,
                         const float* __restrict__ W0, const float* __restrict__ Wm,
                         const unsigned* __restrict__ ei) {
    __shared__ float tile[32][33];
    const int tid = threadIdx.x;
    if (blockIdx.x == 0 && tid == 0) {
        int is64 = 1;
        for (int i = 0; i < 512; i++)
            if (ei[2 * i + 1] != 0u) { is64 = 0; break; }
        g_idx64 = is64;
    }
    const int bid = blockIdx.x;
    if (bid < 608) {
        const float* W; __nv_bfloat16* B;
        int row0, ldW, Ksrc, Kpad, tn, tk;
        if (bid < 32)       { W = Wx; B = g_Bx;  row0 = 0;   ldW = 128; Ksrc = 256; Kpad = 256; tn = bid >> 3;         tk = bid & 7; }
        else if (bid < 64)  { W = W0; B = g_B0a; row0 = 0;   ldW = 256; Ksrc = 128; Kpad = 128; tn = (bid - 32) >> 2;  tk = (bid - 32) & 3; }
        else if (bid < 96)  { W = W0; B = g_B0b; row0 = 128; ldW = 256; Ksrc = 128; Kpad = 128; tn = (bid - 64) >> 2;  tk = (bid - 64) & 3; }
        else {
            int b = bid - 96, L = b >> 6, t = b & 63;
            W = Wm + (size_t)L * 65536; B = &g_Bm[L][0];
            row0 = 0; ldW = 256; Ksrc = 256; Kpad = 256; tn = t >> 3; tk = t & 7;
        }
        const int n0 = tn * 32, k0 = tk * 32;
        const int tx = tid & 31, ty = tid >> 5;     // 32 x 8
        #pragma unroll
        for (int r = 0; r < 32; r += 8) {
            int k = k0 + ty + r;
            tile[ty + r][tx] = (k < Ksrc) ? W[(size_t)(row0 + k) * ldW + n0 + tx] : 0.f;
        }
        __syncthreads();
        #pragma unroll
        for (int r = 0; r < 32; r += 8) {
            int n = n0 + ty + r;
            B[(size_t)n * Kpad + k0 + tx] = __float2bfloat16(tile[tx][ty + r]);
        }
    }
    // B0c image: [n][k] bf16, 4096 elements
    for (int i = blockIdx.x * blockDim.x + tid; i < 4096; i += gridDim.x * blockDim.x) {
        int n = i >> 4, k = i & 15;
        g_B0c[i] = __float2bfloat16(W0[(size_t)(256 + k) * 256 + n]);
    }
    for (int i = blockIdx.x * blockDim.x + tid; i < NNODES * 256; i += gridDim.x * blockDim.x)
        g_xb[i] = __float2bfloat16(x[i]);
}

// ============================ generic bf16 HMMA GEMM (prep stages) ============================
template <int K, int NOUT, bool LEAKY, bool HASBIAS, bool DUAL>
__global__ void __launch_bounds__(256)
gemm_mma(const __nv_bfloat16* __restrict__ A, const __nv_bfloat16* __restrict__ Bin,
         const __nv_bfloat16* __restrict__ B2, const float* __restrict__ bias,
         __nv_bfloat16* __restrict__ Out1, __nv_bfloat16* __restrict__ Out2) {
    static_assert(K % 64 == 0, "");
    constexpr int KT = K / 64;
    extern __shared__ char smem[];
    const uint32_t sb = smem_u32(smem);
    constexpr uint32_t STAGE = 32768, BOFF = 16384;

    const __nv_bfloat16* B = (DUAL && blockIdx.z) ? B2 : Bin;
    __nv_bfloat16* Out = (DUAL && blockIdx.z) ? Out2 : Out1;

    const int tid = threadIdx.x;
    const int lane = tid & 31, warp = tid >> 5;
    const int warp_m = warp & 1;
    const int warp_n = warp >> 1;
    const size_t m0 = (size_t)blockIdx.x * 128;
    const int n0 = blockIdx.y * 128;

    float acc[4][4][4];
    #pragma unroll
    for (int i = 0; i < 4; i++)
        #pragma unroll
        for (int j = 0; j < 4; j++)
            #pragma unroll
            for (int q = 0; q < 4; q++) acc[i][j][q] = 0.f;

    auto load_stage = [&](int stage, int kt) {
        const uint32_t base = sb + stage * STAGE;
        #pragma unroll
        for (int i = 0; i < 4; i++) {
            int idx = tid + i * 256;
            int r = idx >> 3, c8 = idx & 7;
            uint32_t dst = base + r * 128 + (((c8 ^ (r & 7))) << 4);
            cp16(dst, A + (m0 + r) * K + kt * 64 + c8 * 8);
        }
        #pragma unroll
        for (int i = 0; i < 4; i++) {
            int idx = tid + i * 256;
            int r = idx >> 3, c8 = idx & 7;
            uint32_t dst = base + BOFF + r * 128 + (((c8 ^ (r & 7))) << 4);
            cp16(dst, B + (size_t)(n0 + r) * K + kt * 64 + c8 * 8);
        }
    };

    load_stage(0, 0);
    cp_commit();

    for (int kt = 0; kt < KT; kt++) {
        if (kt + 1 < KT) { load_stage((kt + 1) & 1, kt + 1); cp_commit(); cp_wait<1>(); }
        else             { cp_wait<0>(); }
        __syncthreads();

        const uint32_t abase = sb + (kt & 1) * STAGE;
        const uint32_t bbase = abase + BOFF;
        #pragma unroll
        for (int ks = 0; ks < 4; ks++) {
            uint32_t af[4][4];
            #pragma unroll
            for (int mi = 0; mi < 4; mi++) {
                int r = warp_m * 64 + mi * 16 + (lane & 15);
                int c8 = ks * 2 + (lane >> 4);
                ldm_x4(af[mi], abase + r * 128 + ((c8 ^ (r & 7)) << 4));
            }
            uint32_t bf2[4][2];
            #pragma unroll
            for (int ni = 0; ni < 4; ni++) {
                int r = warp_n * 32 + ni * 8 + (lane & 7);
                int c8 = ks * 2 + ((lane >> 3) & 1);
                ldm_x2(bf2[ni], bbase + r * 128 + ((c8 ^ (r & 7)) << 4));
            }
            #pragma unroll
            for (int mi = 0; mi < 4; mi++)
                #pragma unroll
                for (int ni = 0; ni < 4; ni++)
                    mma_bf16(acc[mi][ni], af[mi], bf2[ni]);
        }
        __syncthreads();
    }

    const int g = lane >> 2;
    #pragma unroll
    for (int ni = 0; ni < 4; ni++) {
        const int col = n0 + warp_n * 32 + ni * 8 + ((lane & 3) << 1);
        float bb0 = 0.f, bb1 = 0.f;
        if (HASBIAS) { bb0 = __ldg(bias + col); bb1 = __ldg(bias + col + 1); }
        #pragma unroll
        for (int mi = 0; mi < 4; mi++) {
            const size_t r0 = m0 + warp_m * 64 + mi * 16 + g;
            float v0 = acc[mi][ni][0] + bb0, v1 = acc[mi][ni][1] + bb1;
            float v2 = acc[mi][ni][2] + bb0, v3 = acc[mi][ni][3] + bb1;
            if (LEAKY) {
                v0 = v0 >= 0.f ? v0 : 0.01f * v0;  v1 = v1 >= 0.f ? v1 : 0.01f * v1;
                v2 = v2 >= 0.f ? v2 : 0.01f * v2;  v3 = v3 >= 0.f ? v3 : 0.01f * v3;
            }
            __nv_bfloat162 p0 = __floats2bfloat162_rn(v0, v1);
            __nv_bfloat162 p1 = __floats2bfloat162_rn(v2, v3);
            *(uint32_t*)(Out + r0 * NOUT + col)       = *(uint32_t*)&p0;
            *(uint32_t*)(Out + (r0 + 8) * NOUT + col) = *(uint32_t*)&p1;
        }
    }
}

// ============================ gather + ea-matvec (tensor core) + combine ============================
// Block = 128 edges, 8 warps; warp = one m16 tile x 256 cols in 4 chunks of 64.
// ea matvec done with mma.m16n8k16 (K=16 exactly): A frags from ea directly,
// B frags from pre-transposed B0c [n][k] image (L1-resident, 8KB).
__global__ void __launch_bounds__(256)
gather_mma(const int* __restrict__ ei, const float* __restrict__ ea,
           const __nv_bfloat16* __restrict__ B0c, const float* __restrict__ bias0,
           const __nv_bfloat16* __restrict__ gr, const __nv_bfloat16* __restrict__ gc,
           __nv_bfloat16* __restrict__ h0) {
    __shared__ int srow[128], scol[128];
    const int t = threadIdx.x, lane = t & 31, warp = t >> 5;
    const long e0 = (long)blockIdx.x * 128;
    const int is64 = g_idx64;
    if (t < 128) {
        long e = e0 + t;
        srow[t] = is64 ? ei[2 * e] : ei[e];
    } else {
        int tt = t - 128;
        long e = e0 + tt;
        scol[tt] = is64 ? ei[2 * (NEDGES + e)] : ei[NEDGES + e];
    }
    __syncthreads();

    const int g = lane >> 2, j = lane & 3;
    const int le_g = warp * 16 + g;       // local edge (row g of m16 tile)
    const int le_h = le_g + 8;            // row g+8

    // A fragments from ea fp32 (K=16, one mma k-step)
    const float* eaB = ea + (e0 + (long)warp * 16) * 16;
    uint32_t a[4];
    {
        float2 x0 = *(const float2*)(eaB + g * 16 + 2 * j);
        float2 x1 = *(const float2*)(eaB + (g + 8) * 16 + 2 * j);
        float2 x2 = *(const float2*)(eaB + g * 16 + 2 * j + 8);
        float2 x3 = *(const float2*)(eaB + (g + 8) * 16 + 2 * j + 8);
        __nv_bfloat162 p;
        p = __floats2bfloat162_rn(x0.x, x0.y); a[0] = *(uint32_t*)&p;
        p = __floats2bfloat162_rn(x1.x, x1.y); a[1] = *(uint32_t*)&p;
        p = __floats2bfloat162_rn(x2.x, x2.y); a[2] = *(uint32_t*)&p;
        p = __floats2bfloat162_rn(x3.x, x3.y); a[3] = *(uint32_t*)&p;
    }

    const size_t rgo = (size_t)srow[le_g] * 256, cgo = (size_t)scol[le_g] * 256;
    const size_t rho = (size_t)srow[le_h] * 256, cho = (size_t)scol[le_h] * 256;
    __nv_bfloat16* hg = h0 + (size_t)(e0 + le_g) * 256;
    __nv_bfloat16* hh = h0 + (size_t)(e0 + le_h) * 256;

    #pragma unroll
    for (int ch = 0; ch < 4; ch++) {
        float acc[8][4];
        #pragma unroll
        for (int nt = 0; nt < 8; nt++) {
            const int nb = ch * 64 + nt * 8;
            // B fragment direct from [n][k] image (row.col layout)
            uint32_t b[2];
            const __nv_bfloat16* bp = B0c + (size_t)(nb + g) * 16 + 2 * j;
            b[0] = *(const uint32_t*)bp;
            b[1] = *(const uint32_t*)(bp + 8);
            float2 bb = *(const float2*)(bias0 + nb + 2 * j);
            acc[nt][0] = bb.x; acc[nt][1] = bb.y; acc[nt][2] = bb.x; acc[nt][3] = bb.y;
            mma_bf16(acc[nt], a, b);
        }
        #pragma unroll
        for (int nt = 0; nt < 8; nt++) {
            const int c = ch * 64 + nt * 8 + 2 * j;
            // row g
            {
                float2 gv = __bfloat1622float2(*(const __nv_bfloat162*)(gr + rgo + c));
                float2 cv = __bfloat1622float2(*(const __nv_bfloat162*)(gc + cgo + c));
                float v0 = acc[nt][0] + gv.x + cv.x;
                float v1 = acc[nt][1] + gv.y + cv.y;
                v0 = v0 >= 0.f ? v0 : 0.01f * v0;
                v1 = v1 >= 0.f ? v1 : 0.01f * v1;
                __nv_bfloat162 p = __floats2bfloat162_rn(v0, v1);
                *(uint32_t*)(hg + c) = *(uint32_t*)&p;
            }
            // row g+8
            {
                float2 gv = __bfloat1622float2(*(const __nv_bfloat162*)(gr + rho + c));
                float2 cv = __bfloat1622float2(*(const __nv_bfloat162*)(gc + cho + c));
                float v0 = acc[nt][2] + gv.x + cv.x;
                float v1 = acc[nt][3] + gv.y + cv.y;
                v0 = v0 >= 0.f ? v0 : 0.01f * v0;
                v1 = v1 >= 0.f ? v1 : 0.01f * v1;
                __nv_bfloat162 p = __floats2bfloat162_rn(v0, v1);
                *(uint32_t*)(hh + c) = *(uint32_t*)&p;
            }
        }
    }
}

// ============================ fused 8 mid layers + head (paired groups, named barriers) ============================
// Frozen at the R11 winner.
__global__ void __launch_bounds__(512, 1)
fused_mid(const __nv_bfloat16* __restrict__ h0, const __nv_bfloat16* __restrict__ Bm,
          const float* __restrict__ bm, const float* __restrict__ Wl,
          const float* __restrict__ bl, float* __restrict__ out) {
    extern __shared__ char smem[];
    const uint32_t sb = smem_u32(smem);
    constexpr uint32_t RINGOFF = 65536;               // ring: 4 x 32KB at [64K, 192K)
    constexpr uint32_t PARAM = 65536 + 131072;
    float* sbias = (float*)(smem + PARAM);            // 8 x 256 fp32
    float* sWl   = (float*)(smem + PARAM + 8192);     // 256 x 3 fp32
    float* sbl   = (float*)(smem + PARAM + 8192 + 3072);

    const int tid = threadIdx.x, lane = tid & 31, warp = tid >> 5;
    const int warp_m = warp >> 2;                     // 0..3 -> M offset *32
    const int warp_n = warp & 3;                      // 0..3 -> N offset *64
    const size_t m0 = (size_t)blockIdx.x * 128;

    for (int i = tid; i < 2048; i += 512) sbias[i] = bm[i];
    for (int i = tid; i < 768; i += 512) sWl[i] = Wl[i];
    if (tid < 3) sbl[tid] = bl[tid];

    auto loadB = [&](int s) {
        const uint32_t base = sb + RINGOFF + (uint32_t)(s & 3) * 32768u;
        const __nv_bfloat16* src = Bm + (size_t)(s >> 2) * 65536 + (s & 3) * 64;
        #pragma unroll
        for (int i = 0; i < 4; i++) {
            int idx = tid + i * 512;
            int r = idx >> 3, c8 = idx & 7;
            cp16(base + r * 128 + ((c8 ^ (r & 7)) << 4), src + (size_t)r * 256 + c8 * 8);
        }
    };

    // A tile (h0, 128x256) -> A region as 4 chunks of [128][64], XOR swizzle
    #pragma unroll
    for (int kc = 0; kc < 4; kc++)
        #pragma unroll
        for (int i = 0; i < 2; i++) {
            int idx = tid + i * 512;
            int r = idx >> 3, c8 = idx & 7;
            cp16(sb + kc * 16384 + r * 128 + ((c8 ^ (r & 7)) << 4),
                 h0 + (m0 + r) * 256 + kc * 64 + c8 * 8);
        }
    loadB(0); loadB(1);
    cp_commit();                 // C1 = A + group0

    const int g = lane >> 2, j = lane & 3;
    const int rr_lo = ((lane >> 4) << 3) + (lane & 7);
    const int ar_lo = warp_m * 32 + (lane & 15);

    for (int l = 0; l < 8; ++l) {
        float acc[2][8][4];
        #pragma unroll
        for (int nt = 0; nt < 8; nt++) {
            float2 bb = *(const float2*)(sbias + (l << 8) + warp_n * 64 + 8 * nt + 2 * j);
            #pragma unroll
            for (int mi = 0; mi < 2; mi++) {
                acc[mi][nt][0] = bb.x; acc[mi][nt][1] = bb.y;
                acc[mi][nt][2] = bb.x; acc[mi][nt][3] = bb.y;
            }
        }
        #pragma unroll
        for (int gg = 0; gg < 2; gg++) {
            const int grp = 2 * l + gg;
            cp_wait<0>();
            __syncthreads();
            if (grp + 1 < 16) { loadB(2 * (grp + 1)); loadB(2 * (grp + 1) + 1); }
            cp_commit();
            #pragma unroll
            for (int khh = 0; khh < 2; khh++) {
                const int kh = gg * 2 + khh;
                const int s = l * 4 + kh;
                const uint32_t bbase = sb + RINGOFF + (uint32_t)(s & 3) * 32768u;
                const uint32_t achk = sb + kh * 16384;
                #pragma unroll
                for (int ksl = 0; ksl < 4; ksl++) {
                    const int cca = ksl * 2 + (lane >> 4);
                    uint32_t a0[4], a1[4];
                    int r0 = ar_lo;
                    ldm_x4(a0, achk + r0 * 128 + ((cca ^ (r0 & 7)) << 4));
                    int r1 = ar_lo + 16;
                    ldm_x4(a1, achk + r1 * 128 + ((cca ^ (r1 & 7)) << 4));
                    const int ccb = ksl * 2 + ((lane >> 3) & 1);
                    #pragma unroll
                    for (int bt = 0; bt < 4; bt++) {
                        int rr = warp_n * 64 + bt * 16 + rr_lo;
                        uint32_t bf[4];
                        ldm_x4(bf, bbase + rr * 128 + ((ccb ^ (rr & 7)) << 4));
                        mma_bf16(acc[0][2 * bt],     a0, bf);
                        mma_bf16(acc[0][2 * bt + 1], a0, bf + 2);
                        mma_bf16(acc[1][2 * bt],     a1, bf);
                        mma_bf16(acc[1][2 * bt + 1], a1, bf + 2);
                    }
                }
            }
        }
        asm volatile("bar.sync %0, %1;" :: "r"(1 + warp_m), "r"(128) : "memory");
        #pragma unroll
        for (int mi = 0; mi < 2; mi++) {
            const int r  = warp_m * 32 + mi * 16 + g;
            const int r2 = r + 8;
            #pragma unroll
            for (int nt = 0; nt < 8; nt++) {
                float v0 = acc[mi][nt][0], v1 = acc[mi][nt][1];
                float v2 = acc[mi][nt][2], v3 = acc[mi][nt][3];
                v0 = v0 >= 0.f ? v0 : 0.01f * v0;  v1 = v1 >= 0.f ? v1 : 0.01f * v1;
                v2 = v2 >= 0.f ? v2 : 0.01f * v2;  v3 = v3 >= 0.f ? v3 : 0.01f * v3;
                __nv_bfloat162 p0 = __floats2bfloat162_rn(v0, v1);
                __nv_bfloat162 p1 = __floats2bfloat162_rn(v2, v3);
                const int c = warp_n * 64 + nt * 8;
                const int kc = c >> 6, c8s = (c >> 3) & 7;
                *(uint32_t*)(smem + kc * 16384 + r * 128 + ((c8s ^ (r & 7)) << 4) + 4 * j) =
                    *(uint32_t*)&p0;
                *(uint32_t*)(smem + kc * 16384 + r2 * 128 + ((c8s ^ (r2 & 7)) << 4) + 4 * j) =
                    *(uint32_t*)&p1;
            }
        }
    }
    __syncthreads();

    // ---- fused head (warps 0-7): logits + log_softmax ----
    if (warp < 8) {
        uint32_t pa[32][2];
        #pragma unroll
        for (int s = 0; s < 16; s++) {
            int rr = warp * 16 + (lane & 15);
            int cc = (s & 3) * 2 + (lane >> 4);
            uint32_t f[4];
            ldm_x4(f, sb + (s >> 2) * 16384 + rr * 128 + ((cc ^ (rr & 7)) << 4));
            pa[2 * s][0] = f[0]; pa[2 * s][1] = f[1];
            pa[2 * s + 1][0] = f[2]; pa[2 * s + 1][1] = f[3];
        }
        float a3[2][3] = {{0.f, 0.f, 0.f}, {0.f, 0.f, 0.f}};
        #pragma unroll
        for (int t = 0; t < 32; t++) {
            float2 x = __bfloat1622float2(*(__nv_bfloat162*)&pa[t][0]);
            float2 y = __bfloat1622float2(*(__nv_bfloat162*)&pa[t][1]);
            const int c0 = 8 * t + 2 * j;
            float w00 = sWl[c0 * 3 + 0], w01 = sWl[c0 * 3 + 1], w02 = sWl[c0 * 3 + 2];
            float w10 = sWl[c0 * 3 + 3], w11 = sWl[c0 * 3 + 4], w12 = sWl[c0 * 3 + 5];
            a3[0][0] += x.x * w00 + x.y * w10;
            a3[0][1] += x.x * w01 + x.y * w11;
            a3[0][2] += x.x * w02 + x.y * w12;
            a3[1][0] += y.x * w00 + y.y * w10;
            a3[1][1] += y.x * w01 + y.y * w11;
            a3[1][2] += y.x * w02 + y.y * w12;
        }
        #pragma unroll
        for (int off = 1; off <= 2; off <<= 1) {
            #pragma unroll
            for (int r = 0; r < 2; r++)
                #pragma unroll
                for (int c = 0; c < 3; c++)
                    a3[r][c] += __shfl_xor_sync(0xffffffffu, a3[r][c], off);
        }
        if (j == 0) {
            const float bb0 = sbl[0], bb1 = sbl[1], bb2 = sbl[2];
            #pragma unroll
            for (int r = 0; r < 2; r++) {
                size_t e = m0 + warp * 16 + g + 8 * r;
                float l0 = a3[r][0] + bb0, l1 = a3[r][1] + bb1, l2 = a3[r][2] + bb2;
                float m = fmaxf(l0, fmaxf(l1, l2));
                float ls = m + logf(expf(l0 - m) + expf(l1 - m) + expf(l2 - m));
                out[e * 3 + 0] = l0 - ls;
                out[e * 3 + 1] = l1 - ls;
                out[e * 3 + 2] = l2 - ls;
            }
        }
    }
}

// ============================ host ============================
extern "C" void kernel_launch(void* const* d_in, const int* in_sizes, int n_in,
                              void* d_out, int out_size) {
    const float* x  = (const float*)d_in[0];
    const int*   ei = (const int*)d_in[1];
    const float* ea = (const float*)d_in[2];
    const float* Wx = (const float*)d_in[3];
    const float* bx = (const float*)d_in[4];
    const float* W0 = (const float*)d_in[5];
    const float* b0 = (const float*)d_in[6];
    const float* Wm = (const float*)d_in[7];
    const float* bm = (const float*)d_in[8];
    const float* Wl = (const float*)d_in[9];
    const float* bl = (const float*)d_in[10];
    float* out = (float*)d_out;

    void* p;
    cudaGetSymbolAddress(&p, g_xb);    __nv_bfloat16* xb    = (__nv_bfloat16*)p;
    cudaGetSymbolAddress(&p, g_hnode); __nv_bfloat16* hnode = (__nv_bfloat16*)p;
    cudaGetSymbolAddress(&p, g_grow);  __nv_bfloat16* grow  = (__nv_bfloat16*)p;
    cudaGetSymbolAddress(&p, g_gcol);  __nv_bfloat16* gcol  = (__nv_bfloat16*)p;
    cudaGetSymbolAddress(&p, g_h0);    __nv_bfloat16* h0p   = (__nv_bfloat16*)p;
    cudaGetSymbolAddress(&p, g_Bx);    __nv_bfloat16* Bx    = (__nv_bfloat16*)p;
    cudaGetSymbolAddress(&p, g_B0a);   __nv_bfloat16* B0a   = (__nv_bfloat16*)p;
    cudaGetSymbolAddress(&p, g_B0b);   __nv_bfloat16* B0b   = (__nv_bfloat16*)p;
    cudaGetSymbolAddress(&p, g_B0c);   __nv_bfloat16* B0c   = (__nv_bfloat16*)p;
    cudaGetSymbolAddress(&p, g_Bm);    __nv_bfloat16* Bm    = (__nv_bfloat16*)p;

    constexpr int SMEM = 65536;
    constexpr int FSMEM = 65536 + 131072 + 8192 + 3072 + 16;   // 207,904
    cudaFuncSetAttribute(gemm_mma<256, 128, true,  true,  false>, cudaFuncAttributeMaxDynamicSharedMemorySize, SMEM);
    cudaFuncSetAttribute(gemm_mma<128, 256, false, false, true >, cudaFuncAttributeMaxDynamicSharedMemorySize, SMEM);
    cudaFuncSetAttribute(fused_mid, cudaFuncAttributeMaxDynamicSharedMemorySize, FSMEM);

    // 1: all prep (weight transposes + B0c image + x -> bf16 + idx detect)
    prep_all<<<4096, 256>>>(x, Wx, W0, Wm, (const unsigned*)ei);
    // 2: node MLP: h_node = leaky(x @ Wx + bx)
    gemm_mma<256, 128, true, true, false><<<dim3(NNODES / 128, 1, 1), 256, SMEM>>>(
        xb, Bx, nullptr, bx, hnode, nullptr);
    // 3: node-level edge-GEMM precompute: grow/gcol in one dual launch
    gemm_mma<128, 256, false, false, true><<<dim3(NNODES / 128, 2, 2), 256, SMEM>>>(
        hnode, B0a, B0b, nullptr, grow, gcol);
    // 4: gather + ea matvec (tensor core) + combine + leaky -> h0
    gather_mma<<<NEDGES / 128, 256>>>(ei, ea, B0c, b0, grow, gcol, h0p);
    // 5: fused: 8 hidden layers + head + log_softmax
    fused_mid<<<NEDGES / 128, 512, FSMEM>>>(h0p, Bm, bm, Wl, bl, out);
}

// round 16
// speedup vs baseline: 1.0645x; 1.0448x over previous
#include <cuda_runtime.h>
#include <cuda_bf16.h>
#include <cstdint>

#define NNODES 65536
#define NEDGES 262144

// ============================ device scratch ============================
__device__ __align__(256) __nv_bfloat16 g_xb   [NNODES * 256];
__device__ __align__(256) __nv_bfloat16 g_hnode[NNODES * 128];
__device__ __align__(256) __nv_bfloat16 g_grow [NNODES * 256];
__device__ __align__(256) __nv_bfloat16 g_gcol [NNODES * 256];
__device__ __align__(256) __nv_bfloat16 g_h0   [(size_t)NEDGES * 256];
__device__ __align__(256) __nv_bfloat16 g_Bx [128 * 256];
__device__ __align__(256) __nv_bfloat16 g_B0a[256 * 128];
__device__ __align__(256) __nv_bfloat16 g_B0b[256 * 128];
__device__ __align__(256) __nv_bfloat16 g_B0c[256 * 16];   // W0c^T: [n][k], k contiguous
__device__ __align__(256) __nv_bfloat16 g_Bm [8][256 * 256];
__device__ int g_idx64;

// ============================ PTX helpers (base PTX only) ============================
__device__ __forceinline__ uint32_t smem_u32(const void* p) {
    uint32_t a;
    asm("{ .reg .u64 t; cvta.to.shared.u64 t, %1; cvt.u32.u64 %0, t; }" : "=r"(a) : "l"(p));
    return a;
}
__device__ __forceinline__ void cp16(uint32_t dst, const void* src) {
    asm volatile("cp.async.cg.shared.global [%0], [%1], 16;" :: "r"(dst), "l"(src));
}
__device__ __forceinline__ void cp_commit() {
    asm volatile("cp.async.commit_group;" ::: "memory");
}
template <int N>
__device__ __forceinline__ void cp_wait() {
    asm volatile("cp.async.wait_group %0;" :: "n"(N) : "memory");
}
__device__ __forceinline__ void ldm_x4(uint32_t* r, uint32_t addr) {
    asm volatile("ldmatrix.sync.aligned.m8n8.x4.shared.b16 {%0,%1,%2,%3}, [%4];"
                 : "=r"(r[0]), "=r"(r[1]), "=r"(r[2]), "=r"(r[3]) : "r"(addr));
}
__device__ __forceinline__ void ldm_x2(uint32_t* r, uint32_t addr) {
    asm volatile("ldmatrix.sync.aligned.m8n8.x2.shared.b16 {%0,%1}, [%2];"
                 : "=r"(r[0]), "=r"(r[1]) : "r"(addr));
}
__device__ __forceinline__ void mma_bf16(float* c, const uint32_t* a, const uint32_t* b) {
    asm volatile(
        "mma.sync.aligned.m16n8k16.row.col.f32.bf16.bf16.f32 "
        "{%0,%1,%2,%3}, {%4,%5,%6,%7}, {%8,%9}, {%0,%1,%2,%3};"
        : "+f"(c[0]), "+f"(c[1]), "+f"(c[2]), "+f"(c[3])
        : "r"(a[0]), "r"(a[1]), "r"(a[2]), "r"(a[3]), "r"(b[0]), "r"(b[1]));
}

// ============================ prep: weights + x conversion + idx detect (one launch) ============================
__global__ void prep_all(const float* __restrict__ x, const float* __restrict__ Wx,
                         const float* __restrict__ W0, const float* __restrict__ Wm,
                         const unsigned* __restrict__ ei) {
    __shared__ float tile[32][33];
    const int tid = threadIdx.x;
    if (blockIdx.x == 0 && tid == 0) {
        int is64 = 1;
        for (int i = 0; i < 512; i++)
            if (ei[2 * i + 1] != 0u) { is64 = 0; break; }
        g_idx64 = is64;
    }
    const int bid = blockIdx.x;
    if (bid < 608) {
        const float* W; __nv_bfloat16* B;
        int row0, ldW, Ksrc, Kpad, tn, tk;
        if (bid < 32)       { W = Wx; B = g_Bx;  row0 = 0;   ldW = 128; Ksrc = 256; Kpad = 256; tn = bid >> 3;         tk = bid & 7; }
        else if (bid < 64)  { W = W0; B = g_B0a; row0 = 0;   ldW = 256; Ksrc = 128; Kpad = 128; tn = (bid - 32) >> 2;  tk = (bid - 32) & 3; }
        else if (bid < 96)  { W = W0; B = g_B0b; row0 = 128; ldW = 256; Ksrc = 128; Kpad = 128; tn = (bid - 64) >> 2;  tk = (bid - 64) & 3; }
        else {
            int b = bid - 96, L = b >> 6, t = b & 63;
            W = Wm + (size_t)L * 65536; B = &g_Bm[L][0];
            row0 = 0; ldW = 256; Ksrc = 256; Kpad = 256; tn = t >> 3; tk = t & 7;
        }
        const int n0 = tn * 32, k0 = tk * 32;
        const int tx = tid & 31, ty = tid >> 5;     // 32 x 8
        #pragma unroll
        for (int r = 0; r < 32; r += 8) {
            int k = k0 + ty + r;
            tile[ty + r][tx] = (k < Ksrc) ? W[(size_t)(row0 + k) * ldW + n0 + tx] : 0.f;
        }
        __syncthreads();
        #pragma unroll
        for (int r = 0; r < 32; r += 8) {
            int n = n0 + ty + r;
            B[(size_t)n * Kpad + k0 + tx] = __float2bfloat16(tile[tx][ty + r]);
        }
    }
    // B0c image: [n][k] bf16, 4096 elements
    for (int i = blockIdx.x * blockDim.x + tid; i < 4096; i += gridDim.x * blockDim.x) {
        int n = i >> 4, k = i & 15;
        g_B0c[i] = __float2bfloat16(W0[(size_t)(256 + k) * 256 + n]);
    }
    for (int i = blockIdx.x * blockDim.x + tid; i < NNODES * 256; i += gridDim.x * blockDim.x)
        g_xb[i] = __float2bfloat16(x[i]);
}

// ============================ generic bf16 HMMA GEMM (prep stages) ============================
template <int K, int NOUT, bool LEAKY, bool HASBIAS, bool DUAL>
__global__ void __launch_bounds__(256)
gemm_mma(const __nv_bfloat16* __restrict__ A, const __nv_bfloat16* __restrict__ Bin,
         const __nv_bfloat16* __restrict__ B2, const float* __restrict__ bias,
         __nv_bfloat16* __restrict__ Out1, __nv_bfloat16* __restrict__ Out2) {
    static_assert(K % 64 == 0, "");
    constexpr int KT = K / 64;
    extern __shared__ char smem[];
    const uint32_t sb = smem_u32(smem);
    constexpr uint32_t STAGE = 32768, BOFF = 16384;

    const __nv_bfloat16* B = (DUAL && blockIdx.z) ? B2 : Bin;
    __nv_bfloat16* Out = (DUAL && blockIdx.z) ? Out2 : Out1;

    const int tid = threadIdx.x;
    const int lane = tid & 31, warp = tid >> 5;
    const int warp_m = warp & 1;
    const int warp_n = warp >> 1;
    const size_t m0 = (size_t)blockIdx.x * 128;
    const int n0 = blockIdx.y * 128;

    float acc[4][4][4];
    #pragma unroll
    for (int i = 0; i < 4; i++)
        #pragma unroll
        for (int j = 0; j < 4; j++)
            #pragma unroll
            for (int q = 0; q < 4; q++) acc[i][j][q] = 0.f;

    auto load_stage = [&](int stage, int kt) {
        const uint32_t base = sb + stage * STAGE;
        #pragma unroll
        for (int i = 0; i < 4; i++) {
            int idx = tid + i * 256;
            int r = idx >> 3, c8 = idx & 7;
            uint32_t dst = base + r * 128 + (((c8 ^ (r & 7))) << 4);
            cp16(dst, A + (m0 + r) * K + kt * 64 + c8 * 8);
        }
        #pragma unroll
        for (int i = 0; i < 4; i++) {
            int idx = tid + i * 256;
            int r = idx >> 3, c8 = idx & 7;
            uint32_t dst = base + BOFF + r * 128 + (((c8 ^ (r & 7))) << 4);
            cp16(dst, B + (size_t)(n0 + r) * K + kt * 64 + c8 * 8);
        }
    };

    load_stage(0, 0);
    cp_commit();

    for (int kt = 0; kt < KT; kt++) {
        if (kt + 1 < KT) { load_stage((kt + 1) & 1, kt + 1); cp_commit(); cp_wait<1>(); }
        else             { cp_wait<0>(); }
        __syncthreads();

        const uint32_t abase = sb + (kt & 1) * STAGE;
        const uint32_t bbase = abase + BOFF;
        #pragma unroll
        for (int ks = 0; ks < 4; ks++) {
            uint32_t af[4][4];
            #pragma unroll
            for (int mi = 0; mi < 4; mi++) {
                int r = warp_m * 64 + mi * 16 + (lane & 15);
                int c8 = ks * 2 + (lane >> 4);
                ldm_x4(af[mi], abase + r * 128 + ((c8 ^ (r & 7)) << 4));
            }
            uint32_t bf2[4][2];
            #pragma unroll
            for (int ni = 0; ni < 4; ni++) {
                int r = warp_n * 32 + ni * 8 + (lane & 7);
                int c8 = ks * 2 + ((lane >> 3) & 1);
                ldm_x2(bf2[ni], bbase + r * 128 + ((c8 ^ (r & 7)) << 4));
            }
            #pragma unroll
            for (int mi = 0; mi < 4; mi++)
                #pragma unroll
                for (int ni = 0; ni < 4; ni++)
                    mma_bf16(acc[mi][ni], af[mi], bf2[ni]);
        }
        __syncthreads();
    }

    const int g = lane >> 2;
    #pragma unroll
    for (int ni = 0; ni < 4; ni++) {
        const int col = n0 + warp_n * 32 + ni * 8 + ((lane & 3) << 1);
        float bb0 = 0.f, bb1 = 0.f;
        if (HASBIAS) { bb0 = __ldg(bias + col); bb1 = __ldg(bias + col + 1); }
        #pragma unroll
        for (int mi = 0; mi < 4; mi++) {
            const size_t r0 = m0 + warp_m * 64 + mi * 16 + g;
            float v0 = acc[mi][ni][0] + bb0, v1 = acc[mi][ni][1] + bb1;
            float v2 = acc[mi][ni][2] + bb0, v3 = acc[mi][ni][3] + bb1;
            if (LEAKY) {
                v0 = v0 >= 0.f ? v0 : 0.01f * v0;  v1 = v1 >= 0.f ? v1 : 0.01f * v1;
                v2 = v2 >= 0.f ? v2 : 0.01f * v2;  v3 = v3 >= 0.f ? v3 : 0.01f * v3;
            }
            __nv_bfloat162 p0 = __floats2bfloat162_rn(v0, v1);
            __nv_bfloat162 p1 = __floats2bfloat162_rn(v2, v3);
            *(uint32_t*)(Out + r0 * NOUT + col)       = *(uint32_t*)&p0;
            *(uint32_t*)(Out + (r0 + 8) * NOUT + col) = *(uint32_t*)&p1;
        }
    }
}

// ============================ gather (vectorized) + ea-matvec (tensor core) + combine ============================
// Block = 128 edges, 8 warps. Phase 1: warp computes its m16x256 ea-matvec tile via mma
// and stores bias+matvec (bf16) into padded SMEM (row pitch 132 words, conflict-free).
// Phase 2: same warp walks its 16 edges with uint4 loads of grow/gcol rows + SMEM row,
// fp32 add + leaky, uint4 store to h0. One LDG.128 covers a full 512B row per source.
__global__ void __launch_bounds__(256)
gather_mma(const int* __restrict__ ei, const float* __restrict__ ea,
           const __nv_bfloat16* __restrict__ B0c, const float* __restrict__ bias0,
           const __nv_bfloat16* __restrict__ gr, const __nv_bfloat16* __restrict__ gc,
           __nv_bfloat16* __restrict__ h0) {
    extern __shared__ uint32_t smv[];          // 128 rows x 132 words (528B pitch) = 67584B
    __shared__ int srow[128], scol[128];
    const int t = threadIdx.x, lane = t & 31, warp = t >> 5;
    const long e0 = (long)blockIdx.x * 128;
    const int is64 = g_idx64;
    if (t < 128) {
        long e = e0 + t;
        srow[t] = is64 ? ei[2 * e] : ei[e];
    } else {
        int tt = t - 128;
        long e = e0 + tt;
        scol[tt] = is64 ? ei[2 * (NEDGES + e)] : ei[NEDGES + e];
    }
    __syncthreads();

    const int g = lane >> 2, j = lane & 3;

    // ---- phase 1: ea matvec (K=16, one mma step) -> SMEM ----
    const float* eaB = ea + (e0 + (long)warp * 16) * 16;
    uint32_t a[4];
    {
        float2 x0 = *(const float2*)(eaB + g * 16 + 2 * j);
        float2 x1 = *(const float2*)(eaB + (g + 8) * 16 + 2 * j);
        float2 x2 = *(const float2*)(eaB + g * 16 + 2 * j + 8);
        float2 x3 = *(const float2*)(eaB + (g + 8) * 16 + 2 * j + 8);
        __nv_bfloat162 p;
        p = __floats2bfloat162_rn(x0.x, x0.y); a[0] = *(uint32_t*)&p;
        p = __floats2bfloat162_rn(x1.x, x1.y); a[1] = *(uint32_t*)&p;
        p = __floats2bfloat162_rn(x2.x, x2.y); a[2] = *(uint32_t*)&p;
        p = __floats2bfloat162_rn(x3.x, x3.y); a[3] = *(uint32_t*)&p;
    }
    const int rbase0 = (warp * 16 + g) * 132;
    const int rbase1 = (warp * 16 + g + 8) * 132;
    #pragma unroll
    for (int ch = 0; ch < 4; ch++) {
        #pragma unroll
        for (int nt = 0; nt < 8; nt++) {
            const int nb = ch * 64 + nt * 8;
            uint32_t b[2];
            const __nv_bfloat16* bp = B0c + (size_t)(nb + g) * 16 + 2 * j;
            b[0] = *(const uint32_t*)bp;
            b[1] = *(const uint32_t*)(bp + 8);
            float2 bb = *(const float2*)(bias0 + nb + 2 * j);
            float acc[4] = {bb.x, bb.y, bb.x, bb.y};
            mma_bf16(acc, a, b);
            __nv_bfloat162 p0 = __floats2bfloat162_rn(acc[0], acc[1]);
            __nv_bfloat162 p1 = __floats2bfloat162_rn(acc[2], acc[3]);
            smv[rbase0 + ch * 32 + nt * 4 + j] = *(uint32_t*)&p0;
            smv[rbase1 + ch * 32 + nt * 4 + j] = *(uint32_t*)&p1;
        }
    }
    __syncwarp();

    // ---- phase 2: vectorized gather-add-leaky-store, 16 edges per warp ----
    #pragma unroll 4
    for (int i = 0; i < 16; i++) {
        const int le = warp * 16 + i;
        const uint4 va = ((const uint4*)(gr + (size_t)srow[le] * 256))[lane];
        const uint4 vb = ((const uint4*)(gc + (size_t)scol[le] * 256))[lane];
        const uint4 vm = *(const uint4*)&smv[le * 132 + lane * 4];
        const uint32_t* pa = (const uint32_t*)&va;
        const uint32_t* pb = (const uint32_t*)&vb;
        const uint32_t* pm = (const uint32_t*)&vm;
        uint4 o;
        uint32_t* po = (uint32_t*)&o;
        #pragma unroll
        for (int w = 0; w < 4; w++) {
            float2 fa = __bfloat1622float2(*(const __nv_bfloat162*)&pa[w]);
            float2 fb = __bfloat1622float2(*(const __nv_bfloat162*)&pb[w]);
            float2 fm = __bfloat1622float2(*(const __nv_bfloat162*)&pm[w]);
            float v0 = fm.x + fa.x + fb.x;
            float v1 = fm.y + fa.y + fb.y;
            v0 = v0 >= 0.f ? v0 : 0.01f * v0;
            v1 = v1 >= 0.f ? v1 : 0.01f * v1;
            __nv_bfloat162 p = __floats2bfloat162_rn(v0, v1);
            po[w] = *(uint32_t*)&p;
        }
        *(uint4*)(h0 + (size_t)(e0 + le) * 256 + lane * 8) = o;
    }
}

// ============================ fused 8 mid layers + head (paired groups, named barriers) ============================
// Frozen at the R11 winner.
__global__ void __launch_bounds__(512, 1)
fused_mid(const __nv_bfloat16* __restrict__ h0, const __nv_bfloat16* __restrict__ Bm,
          const float* __restrict__ bm, const float* __restrict__ Wl,
          const float* __restrict__ bl, float* __restrict__ out) {
    extern __shared__ char smem[];
    const uint32_t sb = smem_u32(smem);
    constexpr uint32_t RINGOFF = 65536;               // ring: 4 x 32KB at [64K, 192K)
    constexpr uint32_t PARAM = 65536 + 131072;
    float* sbias = (float*)(smem + PARAM);            // 8 x 256 fp32
    float* sWl   = (float*)(smem + PARAM + 8192);     // 256 x 3 fp32
    float* sbl   = (float*)(smem + PARAM + 8192 + 3072);

    const int tid = threadIdx.x, lane = tid & 31, warp = tid >> 5;
    const int warp_m = warp >> 2;                     // 0..3 -> M offset *32
    const int warp_n = warp & 3;                      // 0..3 -> N offset *64
    const size_t m0 = (size_t)blockIdx.x * 128;

    for (int i = tid; i < 2048; i += 512) sbias[i] = bm[i];
    for (int i = tid; i < 768; i += 512) sWl[i] = Wl[i];
    if (tid < 3) sbl[tid] = bl[tid];

    auto loadB = [&](int s) {
        const uint32_t base = sb + RINGOFF + (uint32_t)(s & 3) * 32768u;
        const __nv_bfloat16* src = Bm + (size_t)(s >> 2) * 65536 + (s & 3) * 64;
        #pragma unroll
        for (int i = 0; i < 4; i++) {
            int idx = tid + i * 512;
            int r = idx >> 3, c8 = idx & 7;
            cp16(base + r * 128 + ((c8 ^ (r & 7)) << 4), src + (size_t)r * 256 + c8 * 8);
        }
    };

    // A tile (h0, 128x256) -> A region as 4 chunks of [128][64], XOR swizzle
    #pragma unroll
    for (int kc = 0; kc < 4; kc++)
        #pragma unroll
        for (int i = 0; i < 2; i++) {
            int idx = tid + i * 512;
            int r = idx >> 3, c8 = idx & 7;
            cp16(sb + kc * 16384 + r * 128 + ((c8 ^ (r & 7)) << 4),
                 h0 + (m0 + r) * 256 + kc * 64 + c8 * 8);
        }
    loadB(0); loadB(1);
    cp_commit();                 // C1 = A + group0

    const int g = lane >> 2, j = lane & 3;
    const int rr_lo = ((lane >> 4) << 3) + (lane & 7);
    const int ar_lo = warp_m * 32 + (lane & 15);

    for (int l = 0; l < 8; ++l) {
        float acc[2][8][4];
        #pragma unroll
        for (int nt = 0; nt < 8; nt++) {
            float2 bb = *(const float2*)(sbias + (l << 8) + warp_n * 64 + 8 * nt + 2 * j);
            #pragma unroll
            for (int mi = 0; mi < 2; mi++) {
                acc[mi][nt][0] = bb.x; acc[mi][nt][1] = bb.y;
                acc[mi][nt][2] = bb.x; acc[mi][nt][3] = bb.y;
            }
        }
        #pragma unroll
        for (int gg = 0; gg < 2; gg++) {
            const int grp = 2 * l + gg;
            cp_wait<0>();
            __syncthreads();
            if (grp + 1 < 16) { loadB(2 * (grp + 1)); loadB(2 * (grp + 1) + 1); }
            cp_commit();
            #pragma unroll
            for (int khh = 0; khh < 2; khh++) {
                const int kh = gg * 2 + khh;
                const int s = l * 4 + kh;
                const uint32_t bbase = sb + RINGOFF + (uint32_t)(s & 3) * 32768u;
                const uint32_t achk = sb + kh * 16384;
                #pragma unroll
                for (int ksl = 0; ksl < 4; ksl++) {
                    const int cca = ksl * 2 + (lane >> 4);
                    uint32_t a0[4], a1[4];
                    int r0 = ar_lo;
                    ldm_x4(a0, achk + r0 * 128 + ((cca ^ (r0 & 7)) << 4));
                    int r1 = ar_lo + 16;
                    ldm_x4(a1, achk + r1 * 128 + ((cca ^ (r1 & 7)) << 4));
                    const int ccb = ksl * 2 + ((lane >> 3) & 1);
                    #pragma unroll
                    for (int bt = 0; bt < 4; bt++) {
                        int rr = warp_n * 64 + bt * 16 + rr_lo;
                        uint32_t bf[4];
                        ldm_x4(bf, bbase + rr * 128 + ((ccb ^ (rr & 7)) << 4));
                        mma_bf16(acc[0][2 * bt],     a0, bf);
                        mma_bf16(acc[0][2 * bt + 1], a0, bf + 2);
                        mma_bf16(acc[1][2 * bt],     a1, bf);
                        mma_bf16(acc[1][2 * bt + 1], a1, bf + 2);
                    }
                }
            }
        }
        asm volatile("bar.sync %0, %1;" :: "r"(1 + warp_m), "r"(128) : "memory");
        #pragma unroll
        for (int mi = 0; mi < 2; mi++) {
            const int r  = warp_m * 32 + mi * 16 + g;
            const int r2 = r + 8;
            #pragma unroll
            for (int nt = 0; nt < 8; nt++) {
                float v0 = acc[mi][nt][0], v1 = acc[mi][nt][1];
                float v2 = acc[mi][nt][2], v3 = acc[mi][nt][3];
                v0 = v0 >= 0.f ? v0 : 0.01f * v0;  v1 = v1 >= 0.f ? v1 : 0.01f * v1;
                v2 = v2 >= 0.f ? v2 : 0.01f * v2;  v3 = v3 >= 0.f ? v3 : 0.01f * v3;
                __nv_bfloat162 p0 = __floats2bfloat162_rn(v0, v1);
                __nv_bfloat162 p1 = __floats2bfloat162_rn(v2, v3);
                const int c = warp_n * 64 + nt * 8;
                const int kc = c >> 6, c8s = (c >> 3) & 7;
                *(uint32_t*)(smem + kc * 16384 + r * 128 + ((c8s ^ (r & 7)) << 4) + 4 * j) =
                    *(uint32_t*)&p0;
                *(uint32_t*)(smem + kc * 16384 + r2 * 128 + ((c8s ^ (r2 & 7)) << 4) + 4 * j) =
                    *(uint32_t*)&p1;
            }
        }
    }
    __syncthreads();

    // ---- fused head (warps 0-7): logits + log_softmax ----
    if (warp < 8) {
        uint32_t pa[32][2];
        #pragma unroll
        for (int s = 0; s < 16; s++) {
            int rr = warp * 16 + (lane & 15);
            int cc = (s & 3) * 2 + (lane >> 4);
            uint32_t f[4];
            ldm_x4(f, sb + (s >> 2) * 16384 + rr * 128 + ((cc ^ (rr & 7)) << 4));
            pa[2 * s][0] = f[0]; pa[2 * s][1] = f[1];
            pa[2 * s + 1][0] = f[2]; pa[2 * s + 1][1] = f[3];
        }
        float a3[2][3] = {{0.f, 0.f, 0.f}, {0.f, 0.f, 0.f}};
        #pragma unroll
        for (int t = 0; t < 32; t++) {
            float2 x = __bfloat1622float2(*(__nv_bfloat162*)&pa[t][0]);
            float2 y = __bfloat1622float2(*(__nv_bfloat162*)&pa[t][1]);
            const int c0 = 8 * t + 2 * j;
            float w00 = sWl[c0 * 3 + 0], w01 = sWl[c0 * 3 + 1], w02 = sWl[c0 * 3 + 2];
            float w10 = sWl[c0 * 3 + 3], w11 = sWl[c0 * 3 + 4], w12 = sWl[c0 * 3 + 5];
            a3[0][0] += x.x * w00 + x.y * w10;
            a3[0][1] += x.x * w01 + x.y * w11;
            a3[0][2] += x.x * w02 + x.y * w12;
            a3[1][0] += y.x * w00 + y.y * w10;
            a3[1][1] += y.x * w01 + y.y * w11;
            a3[1][2] += y.x * w02 + y.y * w12;
        }
        #pragma unroll
        for (int off = 1; off <= 2; off <<= 1) {
            #pragma unroll
            for (int r = 0; r < 2; r++)
                #pragma unroll
                for (int c = 0; c < 3; c++)
                    a3[r][c] += __shfl_xor_sync(0xffffffffu, a3[r][c], off);
        }
        if (j == 0) {
            const float bb0 = sbl[0], bb1 = sbl[1], bb2 = sbl[2];
            #pragma unroll
            for (int r = 0; r < 2; r++) {
                size_t e = m0 + warp * 16 + g + 8 * r;
                float l0 = a3[r][0] + bb0, l1 = a3[r][1] + bb1, l2 = a3[r][2] + bb2;
                float m = fmaxf(l0, fmaxf(l1, l2));
                float ls = m + logf(expf(l0 - m) + expf(l1 - m) + expf(l2 - m));
                out[e * 3 + 0] = l0 - ls;
                out[e * 3 + 1] = l1 - ls;
                out[e * 3 + 2] = l2 - ls;
            }
        }
    }
}

// ============================ host ============================
extern "C" void kernel_launch(void* const* d_in, const int* in_sizes, int n_in,
                              void* d_out, int out_size) {
    const float* x  = (const float*)d_in[0];
    const int*   ei = (const int*)d_in[1];
    const float* ea = (const float*)d_in[2];
    const float* Wx = (const float*)d_in[3];
    const float* bx = (const float*)d_in[4];
    const float* W0 = (const float*)d_in[5];
    const float* b0 = (const float*)d_in[6];
    const float* Wm = (const float*)d_in[7];
    const float* bm = (const float*)d_in[8];
    const float* Wl = (const float*)d_in[9];
    const float* bl = (const float*)d_in[10];
    float* out = (float*)d_out;

    void* p;
    cudaGetSymbolAddress(&p, g_xb);    __nv_bfloat16* xb    = (__nv_bfloat16*)p;
    cudaGetSymbolAddress(&p, g_hnode); __nv_bfloat16* hnode = (__nv_bfloat16*)p;
    cudaGetSymbolAddress(&p, g_grow);  __nv_bfloat16* grow  = (__nv_bfloat16*)p;
    cudaGetSymbolAddress(&p, g_gcol);  __nv_bfloat16* gcol  = (__nv_bfloat16*)p;
    cudaGetSymbolAddress(&p, g_h0);    __nv_bfloat16* h0p   = (__nv_bfloat16*)p;
    cudaGetSymbolAddress(&p, g_Bx);    __nv_bfloat16* Bx    = (__nv_bfloat16*)p;
    cudaGetSymbolAddress(&p, g_B0a);   __nv_bfloat16* B0a   = (__nv_bfloat16*)p;
    cudaGetSymbolAddress(&p, g_B0b);   __nv_bfloat16* B0b   = (__nv_bfloat16*)p;
    cudaGetSymbolAddress(&p, g_B0c);   __nv_bfloat16* B0c   = (__nv_bfloat16*)p;
    cudaGetSymbolAddress(&p, g_Bm);    __nv_bfloat16* Bm    = (__nv_bfloat16*)p;

    constexpr int SMEM = 65536;
    constexpr int FSMEM = 65536 + 131072 + 8192 + 3072 + 16;   // 207,904
    constexpr int GSMEM = 128 * 132 * 4;                        // 67,584
    cudaFuncSetAttribute(gemm_mma<256, 128, true,  true,  false>, cudaFuncAttributeMaxDynamicSharedMemorySize, SMEM);
    cudaFuncSetAttribute(gemm_mma<128, 256, false, false, true >, cudaFuncAttributeMaxDynamicSharedMemorySize, SMEM);
    cudaFuncSetAttribute(gather_mma, cudaFuncAttributeMaxDynamicSharedMemorySize, GSMEM);
    cudaFuncSetAttribute(fused_mid, cudaFuncAttributeMaxDynamicSharedMemorySize, FSMEM);

    // 1: all prep (weight transposes + B0c image + x -> bf16 + idx detect)
    prep_all<<<4096, 256>>>(x, Wx, W0, Wm, (const unsigned*)ei);
    // 2: node MLP: h_node = leaky(x @ Wx + bx)
    gemm_mma<256, 128, true, true, false><<<dim3(NNODES / 128, 1, 1), 256, SMEM>>>(
        xb, Bx, nullptr, bx, hnode, nullptr);
    // 3: node-level edge-GEMM precompute: grow/gcol in one dual launch
    gemm_mma<128, 256, false, false, true><<<dim3(NNODES / 128, 2, 2), 256, SMEM>>>(
        hnode, B0a, B0b, nullptr, grow, gcol);
    // 4: gather (vectorized) + ea matvec (tensor core) + combine + leaky -> h0
    gather_mma<<<NEDGES / 128, 256, GSMEM>>>(ei, ea, B0c, b0, grow, gcol, h0p);
    // 5: fused: 8 hidden layers + head + log_softmax
    fused_mid<<<NEDGES / 128, 512, FSMEM>>>(h0p, Bm, bm, Wl, bl, out);
}